// round 7
// baseline (speedup 1.0000x reference)
#include <cuda_runtime.h>
#include <cuda_bf16.h>

#define NXX 1024
#define NYY 1024
#define DIMK 128
#define NBLK 256
#define TPX 68

typedef unsigned long long ull;

// ---- scratch globals (no allocation; nothing needs per-replay re-init) ----
__device__ float    g_bmin[NBLK];
__device__ float    g_rpart[NXX * 16];       // row-sum partials [row][bx]
__device__ float    g_cpart[NYY * 16];       // col-sum partials [col][by]
__device__ float    g_p1[NBLK], g_p2[NBLK];
__device__ unsigned g_cnt[3];
__device__ unsigned g_gen[3];

// ---- packed f32x2 helpers ----
__device__ __forceinline__ ull fma2_(ull a, ull b, ull c) {
    ull d; asm("fma.rn.f32x2 %0, %1, %2, %3;" : "=l"(d) : "l"(a), "l"(b), "l"(c)); return d;
}
__device__ __forceinline__ ull add2_(ull a, ull b) {
    ull d; asm("add.rn.f32x2 %0, %1, %2;" : "=l"(d) : "l"(a), "l"(b)); return d;
}
__device__ __forceinline__ float lo_(ull v) { return __uint_as_float((unsigned)(v & 0xFFFFFFFFu)); }
__device__ __forceinline__ float hi_(ull v) { return __uint_as_float((unsigned)(v >> 32)); }

#define NEG1_2 0xBF800000BF800000ULL
#define ABS2   0x7FFFFFFF7FFFFFFFULL

__device__ __forceinline__ float warp_sum(float v) {
#pragma unroll
    for (int o = 16; o > 0; o >>= 1) v += __shfl_xor_sync(0xFFFFFFFFu, v, o);
    return v;
}
__device__ __forceinline__ float warp_min(float v) {
#pragma unroll
    for (int o = 16; o > 0; o >>= 1) v = fminf(v, __shfl_xor_sync(0xFFFFFFFFu, v, o));
    return v;
}

__device__ __forceinline__ void grid_bar(int i) {
    __syncthreads();
    if (threadIdx.x == 0) {
        volatile unsigned* genp = (volatile unsigned*)&g_gen[i];
        unsigned start = *genp;
        __threadfence();
        unsigned my = atomicAdd(&g_cnt[i], 1u);
        if (my == NBLK - 1) {
            g_cnt[i] = 0;
            __threadfence();
            atomicAdd(&g_gen[i], 1u);
        } else {
            while (*genp == start) { }
            __threadfence();
        }
    }
    __syncthreads();
}

// ---------------------------------------------------------------- the kernel
// 256 blocks x 512 threads. Tile 64x64; micro-tile 2 rows x 4 cols per thread.
__global__ __launch_bounds__(512, 2)
void k_all(const float* __restrict__ zx, const float* __restrict__ zy,
           const float* __restrict__ theta, const float* __restrict__ beta,
           float* __restrict__ out, int nout) {
    __shared__ float SH[2 * 64 * TPX];
    __shared__ float s_aux[80];
    float* xs = SH;
    float* ys = SH + 64 * TPX;

    const int tid  = threadIdx.x;
    const int lane = tid & 31, w = tid >> 5;       // w: 0..15
    const int tx   = tid & 15;                     // cols 4tx..4tx+3
    const int ty   = tid >> 4;                     // 0..31, rows 2ty..2ty+1
    const int bid  = blockIdx.x;
    const int bx   = bid & 15, by = bid >> 4;
    const int bi   = by << 6, bj = bx << 6;

    // ================= Phase 1: L1 distances =================
    ull acc[2][4];
#pragma unroll
    for (int i = 0; i < 2; i++)
#pragma unroll
        for (int j = 0; j < 4; j++) acc[i][j] = 0ULL;

    const int row0 = 2 * ty, row1 = 2 * ty + 1;
    const int k0 = (row0 >> 2) & 15, k1 = (row1 >> 2) & 15;

    for (int kc = 0; kc < 2; kc++) {
        if (kc) __syncthreads();
#pragma unroll
        for (int l = tid; l < 1024; l += 512) {
            int r  = l >> 4;
            int dq = l & 15;
            int sw = (dq ^ ((r >> 2) & 15)) << 2;
            float4 vx = *reinterpret_cast<const float4*>(zx + (bi + r) * DIMK + kc * 64 + dq * 4);
            *reinterpret_cast<float4*>(&xs[r * TPX + sw]) = vx;
            float4 vy = *reinterpret_cast<const float4*>(zy + (bj + r) * DIMK + kc * 64 + dq * 4);
            *reinterpret_cast<float4*>(&ys[r * TPX + sw]) = vy;
        }
        __syncthreads();

#pragma unroll 4
        for (int dq = 0; dq < 16; dq++) {
            ulonglong2 av[2], bv[4];
            av[0] = *reinterpret_cast<const ulonglong2*>(&xs[row0 * TPX + ((dq ^ k0) << 2)]);
            av[1] = *reinterpret_cast<const ulonglong2*>(&xs[row1 * TPX + ((dq ^ k1) << 2)]);
            int gy = (dq ^ tx) << 2;
#pragma unroll
            for (int jj = 0; jj < 4; jj++)
                bv[jj] = *reinterpret_cast<const ulonglong2*>(&ys[(4 * tx + jj) * TPX + gy]);
#pragma unroll
            for (int ii = 0; ii < 2; ii++)
#pragma unroll
                for (int jj = 0; jj < 4; jj++) {
                    ull d0 = fma2_(bv[jj].x, NEG1_2, av[ii].x) & ABS2;
                    ull d1 = fma2_(bv[jj].y, NEG1_2, av[ii].y) & ABS2;
                    acc[ii][jj] = add2_(acc[ii][jj], add2_(d0, d1));
                }
        }
    }

    float accv[2][4];
    float mymin = 3.4e38f;
#pragma unroll
    for (int ii = 0; ii < 2; ii++)
#pragma unroll
        for (int jj = 0; jj < 4; jj++) {
            float a = lo_(acc[ii][jj]) + hi_(acc[ii][jj]);
            accv[ii][jj] = a;
            mymin = fminf(mymin, a);
        }
    mymin = warp_min(mymin);
    __syncthreads();                        // xs/ys free
    if (lane == 0) s_aux[w] = mymin;
    __syncthreads();
    if (tid == 0) {
        float m = s_aux[0];
#pragma unroll
        for (int k = 1; k < 16; k++) m = fminf(m, s_aux[k]);
        g_bmin[bid] = m;
    }

    grid_bar(0);

    // ================= Phase 2: exp + row/col sum partials =================
    if (tid < 256) {
        float v = g_bmin[tid];
        v = warp_min(v);
        if (lane == 0) s_aux[w] = v;        // w 0..7
    }
    __syncthreads();
    if (tid == 0) {
        float m = s_aux[0];
#pragma unroll
        for (int k = 1; k < 8; k++) m = fminf(m, s_aux[k]);
        s_aux[64] = m;
    }
    __syncthreads();
    const float mn = s_aux[64];             // e = exp(mn - dist)

    float e[2][4];
#pragma unroll
    for (int ii = 0; ii < 2; ii++)
#pragma unroll
        for (int jj = 0; jj < 4; jj++)
            e[ii][jj] = __expf(mn - accv[ii][jj]);

    // row partials: reduce over tx (half-warp: lanes 0-15 = one ty, 16-31 = next)
#pragma unroll
    for (int ii = 0; ii < 2; ii++) {
        float r = (e[ii][0] + e[ii][1]) + (e[ii][2] + e[ii][3]);
#pragma unroll
        for (int o = 8; o > 0; o >>= 1) r += __shfl_xor_sync(0xFFFFFFFFu, r, o);
        if (tx == 0) g_rpart[(bi + 2 * ty + ii) * 16 + bx] = r;
    }

    // col partials via smem (reduce over 32 ty values)
    float* red = xs;                        // [64][33]
    __syncthreads();
#pragma unroll
    for (int jj = 0; jj < 4; jj++)
        red[(4 * tx + jj) * 33 + ty] = e[0][jj] + e[1][jj];
    __syncthreads();
    if (tid < 64) {
        float c = 0.0f;
#pragma unroll
        for (int k = 0; k < 32; k++) c += red[tid * 33 + k];
        g_cpart[(bj + tid) * 16 + by] = c;
    }

    grid_bar(1);

    // ================= Phase 3: a = er+ec-er*ec =================
    float* rs = ys;
    float* cs = ys + 64;
    if (tid < 64) {
        float t = 0.0f;
#pragma unroll
        for (int k = 0; k < 16; k++) t += g_rpart[(bi + tid) * 16 + k];
        rs[tid] = __fdividef(1.0f, t);
    } else if (tid < 128) {
        int c = tid - 64;
        float t = 0.0f;
#pragma unroll
        for (int k = 0; k < 16; k++) t += g_cpart[(bj + c) * 16 + k];
        cs[c] = __fdividef(1.0f, t);
    }
    __syncthreads();

    float csj[4];
#pragma unroll
    for (int jj = 0; jj < 4; jj++) csj[jj] = cs[4 * tx + jj];

    float p1 = 0.0f, p2 = 0.0f;
#pragma unroll
    for (int ii = 0; ii < 2; ii++) {
        float ri = rs[2 * ty + ii];
#pragma unroll
        for (int jj = 0; jj < 4; jj++) {
            float ev = e[ii][jj];
            float er = ev * ri;
            float ec = ev * csj[jj];
            float a = er + ec - er * ec;
            p1 += a;
            p2 -= a * accv[ii][jj];         // s = -dist
        }
    }
    p1 = warp_sum(p1);
    p2 = warp_sum(p2);
    __syncthreads();
    if (lane == 0) { s_aux[w] = p1; s_aux[16 + w] = p2; }
    __syncthreads();
    if (tid == 0) {
        float a1 = 0.f, a2 = 0.f;
#pragma unroll
        for (int k = 0; k < 16; k++) { a1 += s_aux[k]; a2 += s_aux[16 + k]; }
        g_p1[bid] = a1;
        g_p2[bid] = a2;
    }

    grid_bar(2);

    // ================= Phase 4: block 0 reduces + writes logits =================
    if (bid == 0) {
        if (tid < 256) {
            float q1 = g_p1[tid];
            float q2 = g_p2[tid];
            q1 = warp_sum(q1);
            q2 = warp_sum(q2);
            if (lane == 0) { s_aux[w] = q1; s_aux[16 + w] = q2; }   // w 0..7
        }
        __syncthreads();
        if (tid == 0) {
            float S1 = 0.f, S2 = 0.f;
#pragma unroll
            for (int k = 0; k < 8; k++) { S1 += s_aux[k]; S2 += s_aux[16 + k]; }
            s_aux[64] = S2 / S1;
        }
        __syncthreads();
        if (tid < nout && nout <= 512)
            out[tid] = s_aux[64] * theta[tid] + beta[tid];
    }
}

// ---------------------------------------------------------------- launch
extern "C" void kernel_launch(void* const* d_in, const int* in_sizes, int n_in,
                              void* d_out, int out_size) {
    (void)n_in; (void)in_sizes;
    const float* zx    = (const float*)d_in[0];
    const float* zy    = (const float*)d_in[1];
    const float* theta = (const float*)d_in[2];
    const float* beta  = (const float*)d_in[3];
    float* out = (float*)d_out;

    k_all<<<NBLK, 512>>>(zx, zy, theta, beta, out, out_size);
}